// round 13
// baseline (speedup 1.0000x reference)
#include <cuda_runtime.h>
#include <cuda_fp16.h>
#include <cstdint>

// ---------------------------------------------------------------------------
// NeuroVPR SNN, fully fused: ONE persistent kernel runs L1 GEMM + LIF1 +
// L2 GEMM + LIF2 + L3 GEMM + LIF3 for all T=3 timesteps (rows independent).
// fp16 2-way exact-split arithmetic (proven flip-free R5-R12).
// h1 never touches DRAM (stays in accumulators); spikes stay in smem.
// ---------------------------------------------------------------------------

#define B_ 16384
#define T_ 3
#define D_ 2752
#define H_ 256
#define O_ 100

// ---- scratch ----
__device__ float g_v1[(size_t)B_ * H_];        // [cta][tid][64] private layout
__device__ float g_v2[(size_t)B_ * H_];
__device__ float g_v3[(size_t)B_ * 128];
__device__ __half g_W1s[2 * H_ * D_];
__device__ __half g_W2s[2 * H_ * H_];
__device__ __half g_W3s[2 * 128 * H_];

#define WSCALE 64.0f
#define INV_S1 (1.0f / 4096.0f)
#define INV_S2 (1.0f / 64.0f)

// ======================= helpers =======================
__device__ __forceinline__ uint32_t smem_u32(const void* p) {
    uint32_t a;
    asm("{ .reg .u64 t; cvta.to.shared.u64 t, %1; cvt.u32.u64 %0, t; }"
        : "=r"(a) : "l"(p));
    return a;
}
#define CP_ASYNC16(dst, src) \
    asm volatile("cp.async.cg.shared.global [%0], [%1], 16;" :: "r"(dst), "l"(src))
#define CP_COMMIT() asm volatile("cp.async.commit_group;" ::: "memory")
#define CP_WAIT0() asm volatile("cp.async.wait_group 0;" ::: "memory")
#define CP_WAIT1() asm volatile("cp.async.wait_group 1;" ::: "memory")
#define LDSM4(r0, r1, r2, r3, addr) \
    asm volatile("ldmatrix.sync.aligned.m8n8.x4.shared.b16 {%0,%1,%2,%3}, [%4];" \
        : "=r"(r0), "=r"(r1), "=r"(r2), "=r"(r3) : "r"(addr))
#define MMA16816(d, a, b) \
    asm volatile("mma.sync.aligned.m16n8k16.row.col.f32.f16.f16.f32 " \
        "{%0,%1,%2,%3}, {%4,%5,%6,%7}, {%8,%9}, {%0,%1,%2,%3};" \
        : "+f"((d)[0]), "+f"((d)[1]), "+f"((d)[2]), "+f"((d)[3]) \
        : "r"((a)[0]), "r"((a)[1]), "r"((a)[2]), "r"((a)[3]), "r"((b)[0]), "r"((b)[1]))

__device__ __forceinline__ void split2(float x, __half& h, __half& l) {
    float xs = x * WSCALE;
    h = __float2half_rn(xs);
    l = __float2half_rn(xs - __half2float(h));
}
__device__ __forceinline__ uint32_t pack_h2(__half lo, __half hi) {
    return (uint32_t)__half_as_ushort(lo) | ((uint32_t)__half_as_ushort(hi) << 16);
}
__device__ __forceinline__ void lif_c(float hval, float vin, float& vout, float& sout) {
    float vn = __fadd_rn(vin, __fmul_rn(__fsub_rn(hval, vin), 0.5f));
    bool sp = (vn >= 1.0f);
    vout = sp ? 0.0f : vn;
    sout = sp ? 1.0f : 0.0f;
}
__device__ __forceinline__ uint32_t swz(int r, int c) {
    return (uint32_t)(r * 64 + ((c ^ ((r >> 1) & 3)) << 4));
}

// ======================= weight split kernels =======================
__global__ void split_w_kernel(const float* __restrict__ W, __half* dst, int n) {
    int i = blockIdx.x * 256 + threadIdx.x;
    __half h, l;
    split2(W[i], h, l);
    dst[i] = h; dst[i + n] = l;
}
__global__ void split_w3_kernel(const float* __restrict__ W3) {
    int i = blockIdx.x * 256 + threadIdx.x;
    int r = i >> 8, c = i & 255;
    float w = (r < O_) ? W3[r * H_ + c] : 0.0f;
    __half h, l;
    split2(w, h, l);
    g_W3s[i] = h; g_W3s[i + 128 * H_] = l;
}

// ======================= mega kernel =======================
#define NST1 (D_ / 32)            // 86
#define APL1 8192
#define AB1  (2 * APL1)
#define BPL1 16384
#define STG1 (AB1 + 2 * BPL1)     // 49152
#define SMEMM (3 * STG1)          // 147456
// phase2/3 overlays (phases are barrier-separated):
#define S1OFF 0                   // s1 spikes: 8 chunks x 8192 = 64KB
#define B2OFF 65536               // W2 stages: 2 x 32768
#define S2OFF 0                   // s2 spikes: 64KB (after s1 dead)
#define B3OFF 65536               // W3 stages: 2 x 16384

__global__ void __launch_bounds__(512, 1) mega_snn(
    const float* __restrict__ dvs, const __half* __restrict__ W1s,
    const __half* __restrict__ W2s, const __half* __restrict__ W3s,
    const float* __restrict__ b1, const float* __restrict__ b2,
    const float* __restrict__ b3, float* __restrict__ v1,
    float* __restrict__ v2, float* __restrict__ v3,
    float* __restrict__ out) {
    extern __shared__ char smem[];
    const uint32_t sb = smem_u32(smem);
    const int tid = threadIdx.x;
    const int lane = tid & 31;
    const int wid = tid >> 5;
    const int m0 = blockIdx.x * 128;
    const int mbase = (wid & 3) * 32;
    const int nbase = (wid >> 2) * 64;       // phase1/2: 64-wide N per warp
    const int nbase2 = (wid >> 2) * 32;      // phase3: 32-wide
    const int lr = tid >> 2, lc = tid & 3;

    // private v-state pointers: [cta][tid][...]
    float4* v1p = (float4*)(v1 + ((size_t)blockIdx.x * 512 + tid) * 64);
    float4* v2p = (float4*)(v2 + ((size_t)blockIdx.x * 512 + tid) * 64);
    float4* v3p = (float4*)(v3 + ((size_t)blockIdx.x * 512 + tid) * 32);

    // ldmatrix geometry
    const int a_row = mbase + (lane & 7) + ((lane >> 3) & 1) * 8;
    const int a_chb = (lane >> 4);
    const int b_row = nbase + (lane & 7) + (lane >> 4) * 8;
    const int b_chb = ((lane >> 3) & 1);
    const int b3_row = nbase2 + (lane & 7) + (lane >> 4) * 8;

    float4 ra2[2];

    for (int t = 0; t < T_; ++t) {
        __syncthreads();   // previous phase-3 reads done before buf reuse

        // ================= phase 1: h1 = dvs(t) @ W1^T =================
        float acc[2][8][4];
#pragma unroll
        for (int i = 0; i < 2; ++i)
#pragma unroll
            for (int j = 0; j < 8; ++j)
#pragma unroll
                for (int k = 0; k < 4; ++k) acc[i][j][k] = 0.0f;

        auto ldg_A = [&](int ks) {
            const float* g = dvs + ((size_t)(m0 + lr) * 3 + t) * D_ + ks * 32 + lc * 8;
            ra2[0] = *(const float4*)g;
            ra2[1] = *(const float4*)(g + 4);
        };
        auto sts_A_split = [&](int buf) {
            uint32_t ab = sb + buf * STG1;
            float x[8] = {ra2[0].x, ra2[0].y, ra2[0].z, ra2[0].w,
                          ra2[1].x, ra2[1].y, ra2[1].z, ra2[1].w};
            __half s0[8], s1h[8];
#pragma unroll
            for (int j = 0; j < 8; ++j) split2(x[j], s0[j], s1h[j]);
            uint32_t off = swz(lr, lc);
            uint4 v0 = make_uint4(pack_h2(s0[0], s0[1]), pack_h2(s0[2], s0[3]),
                                  pack_h2(s0[4], s0[5]), pack_h2(s0[6], s0[7]));
            uint4 vv1 = make_uint4(pack_h2(s1h[0], s1h[1]), pack_h2(s1h[2], s1h[3]),
                                   pack_h2(s1h[4], s1h[5]), pack_h2(s1h[6], s1h[7]));
            asm volatile("st.shared.v4.b32 [%0], {%1,%2,%3,%4};" :: "r"(ab + off),
                         "r"(v0.x), "r"(v0.y), "r"(v0.z), "r"(v0.w));
            asm volatile("st.shared.v4.b32 [%0], {%1,%2,%3,%4};" :: "r"(ab + APL1 + off),
                         "r"(vv1.x), "r"(vv1.y), "r"(vv1.z), "r"(vv1.w));
        };
        auto load_B1 = [&](int ks, int buf) {
            int kc = ks * 32;
            uint32_t bb = sb + buf * STG1 + AB1;
#pragma unroll
            for (int u = 0; u < 4; ++u) {
                int f = tid + u * 512;
                int s = f >> 10, rem = f & 1023, r = rem >> 2, c = rem & 3;
                const __half* src = W1s + (size_t)s * (H_ * D_) + (size_t)r * D_ + kc + c * 8;
                CP_ASYNC16(bb + s * BPL1 + swz(r, c), src);
            }
        };
        auto ldsmA = [&](uint32_t ab, int plane, int kk, uint32_t* dst) {
#pragma unroll
            for (int ma = 0; ma < 2; ++ma) {
                uint32_t ad = ab + plane * APL1 + swz(a_row + ma * 16, kk * 2 + a_chb);
                LDSM4(dst[ma * 4 + 0], dst[ma * 4 + 1], dst[ma * 4 + 2], dst[ma * 4 + 3], ad);
            }
        };
        auto ldsmB = [&](uint32_t bb, int pb, int kk, uint32_t* dst) {
#pragma unroll
            for (int h = 0; h < 4; ++h) {
                uint32_t bd = bb + pb * BPL1 + swz(b_row + h * 16, kk * 2 + b_chb);
                LDSM4(dst[h * 4 + 0], dst[h * 4 + 1], dst[h * 4 + 2], dst[h * 4 + 3], bd);
            }
        };
        auto mmaP = [&](const uint32_t* a, const uint32_t* b) {
#pragma unroll
            for (int ma = 0; ma < 2; ++ma)
#pragma unroll
                for (int na = 0; na < 8; ++na)
                    MMA16816(acc[ma][na], &a[ma * 4], &b[na * 2]);
        };
        auto compute1 = [&](int buf) {
            uint32_t ab = sb + buf * STG1;
            uint32_t bb = ab + AB1;
            uint32_t a0[8], a1[8], a0n[8], bx[16], by[16];
            ldsmA(ab, 0, 0, a0);
            ldsmA(ab, 1, 0, a1);
            ldsmB(bb, 0, 0, bx);
            ldsmB(bb, 1, 0, by);
            mmaP(a0, bx);
            mmaP(a1, bx);
            ldsmA(ab, 0, 1, a0n);
            ldsmA(ab, 1, 1, a1);
            ldsmB(bb, 0, 1, bx);
            mmaP(a0, by);
            ldsmB(bb, 1, 1, by);
            mmaP(a0n, bx);
            mmaP(a1, bx);
            mmaP(a0n, by);
        };

        ldg_A(0); sts_A_split(0);
        load_B1(0, 0); CP_COMMIT();
        load_B1(1, 1); CP_COMMIT();
        ldg_A(1);

        int buf = 0;
        for (int ks = 0; ks < NST1; ++ks) {
            int n1 = (buf + 1 == 3) ? 0 : buf + 1;
            int n2 = (n1 + 1 == 3) ? 0 : n1 + 1;
            if (ks + 1 < NST1) sts_A_split(n1);
            if (ks + 2 < NST1) ldg_A(ks + 2);
            if (ks + 1 < NST1) { CP_WAIT1(); } else { CP_WAIT0(); }
            __syncthreads();
            if (ks + 2 < NST1) { load_B1(ks + 2, n2); CP_COMMIT(); }
            compute1(buf);
            buf = n1;
        }

        __syncthreads();   // phase-1 bufs dead

        // prefetch W2 stage 0 (goes to B2OFF, outside s1 area)
        auto load_B2 = [&](int ks, int bf) {
            uint32_t bb = sb + B2OFF + bf * 32768;
#pragma unroll
            for (int u = 0; u < 4; ++u) {
                int f = tid + u * 512;
                int s = f >> 10, rem = f & 1023, r = rem >> 2, c = rem & 3;
                const __half* src = W2s + (size_t)s * (H_ * H_) + (size_t)r * H_ + ks * 32 + c * 8;
                CP_ASYNC16(bb + s * BPL1 + swz(r, c), src);
            }
        };
        load_B2(0, 0); CP_COMMIT();

        // ---- LIF1 epilogue: acc -> spikes in smem (s1), v1 private ----
#pragma unroll
        for (int ma = 0; ma < 2; ++ma) {
#pragma unroll
            for (int na = 0; na < 8; ++na) {
                int col0 = nbase + na * 8 + (lane & 3) * 2;
                const float* a4 = acc[ma][na];
                float4 vin = (t == 0) ? make_float4(0.f, 0.f, 0.f, 0.f)
                                      : v1p[ma * 8 + na];
                float4 vo;
                float hx0 = __fadd_rn(__fmul_rn(a4[0], INV_S1), b1[col0]);
                float hy0 = __fadd_rn(__fmul_rn(a4[1], INV_S1), b1[col0 + 1]);
                float hx1 = __fadd_rn(__fmul_rn(a4[2], INV_S1), b1[col0]);
                float hy1 = __fadd_rn(__fmul_rn(a4[3], INV_S1), b1[col0 + 1]);
                float s0x, s0y, s1x, s1y;
                lif_c(hx0, vin.x, vo.x, s0x);
                lif_c(hy0, vin.y, vo.y, s0y);
                lif_c(hx1, vin.z, vo.z, s1x);
                lif_c(hy1, vin.w, vo.w, s1y);
                v1p[ma * 8 + na] = vo;
#pragma unroll
                for (int h = 0; h < 2; ++h) {
                    int rloc = mbase + ma * 16 + (lane >> 2) + h * 8;
                    int chunk = col0 >> 5, c32 = col0 & 31;
                    uint32_t addr = sb + S1OFF + chunk * 8192 + swz(rloc, c32 >> 3) + (c32 & 7) * 2;
                    uint32_t pk = (h == 0) ? pack_h2(__float2half_rn(s0x), __float2half_rn(s0y))
                                           : pack_h2(__float2half_rn(s1x), __float2half_rn(s1y));
                    asm volatile("st.shared.b32 [%0], %1;" :: "r"(addr), "r"(pk));
                }
            }
        }

        // ================= phase 2: h2 = s1 @ W2^T =================
        float acc2[2][8][4];
#pragma unroll
        for (int i = 0; i < 2; ++i)
#pragma unroll
            for (int j = 0; j < 8; ++j)
#pragma unroll
                for (int k = 0; k < 4; ++k) acc2[i][j][k] = 0.0f;

        for (int ks = 0; ks < 8; ++ks) {
            CP_WAIT0();
            __syncthreads();   // first iter also publishes s1
            if (ks + 1 < 8) { load_B2(ks + 1, (ks + 1) & 1); CP_COMMIT(); }
            uint32_t abase = sb + S1OFF + ks * 8192;
            uint32_t bbase = sb + B2OFF + (ks & 1) * 32768;
#pragma unroll
            for (int kk = 0; kk < 2; ++kk) {
                uint32_t a[8];
#pragma unroll
                for (int ma = 0; ma < 2; ++ma) {
                    uint32_t ad = abase + swz(a_row + ma * 16, kk * 2 + a_chb);
                    LDSM4(a[ma * 4 + 0], a[ma * 4 + 1], a[ma * 4 + 2], a[ma * 4 + 3], ad);
                }
#pragma unroll
                for (int pb = 0; pb < 2; ++pb) {
                    uint32_t b[16];
#pragma unroll
                    for (int h = 0; h < 4; ++h) {
                        uint32_t bd = bbase + pb * BPL1 + swz(b_row + h * 16, kk * 2 + b_chb);
                        LDSM4(b[h * 4 + 0], b[h * 4 + 1], b[h * 4 + 2], b[h * 4 + 3], bd);
                    }
#pragma unroll
                    for (int ma = 0; ma < 2; ++ma)
#pragma unroll
                        for (int na = 0; na < 8; ++na)
                            MMA16816(acc2[ma][na], &a[ma * 4], &b[na * 2]);
                }
            }
        }

        __syncthreads();   // s1/B2 dead; safe to write s2 / load B3

        auto load_B3 = [&](int ks, int bf) {
            uint32_t bb = sb + B3OFF + bf * 16384;
#pragma unroll
            for (int u = 0; u < 2; ++u) {
                int f = tid + u * 512;
                int s = f >> 9, rem = f & 511, r = rem >> 2, c = rem & 3;
                const __half* src = W3s + (size_t)s * (128 * H_) + (size_t)r * H_ + ks * 32 + c * 8;
                CP_ASYNC16(bb + s * 8192 + swz(r, c), src);
            }
        };
        load_B3(0, 0); CP_COMMIT();

        // ---- LIF2 epilogue: acc2 -> s2 smem, v2 private ----
#pragma unroll
        for (int ma = 0; ma < 2; ++ma) {
#pragma unroll
            for (int na = 0; na < 8; ++na) {
                int col0 = nbase + na * 8 + (lane & 3) * 2;
                const float* a4 = acc2[ma][na];
                float4 vin = (t == 0) ? make_float4(0.f, 0.f, 0.f, 0.f)
                                      : v2p[ma * 8 + na];
                float4 vo;
                float hx0 = __fadd_rn(__fmul_rn(a4[0], INV_S2), b2[col0]);
                float hy0 = __fadd_rn(__fmul_rn(a4[1], INV_S2), b2[col0 + 1]);
                float hx1 = __fadd_rn(__fmul_rn(a4[2], INV_S2), b2[col0]);
                float hy1 = __fadd_rn(__fmul_rn(a4[3], INV_S2), b2[col0 + 1]);
                float s0x, s0y, s1x, s1y;
                lif_c(hx0, vin.x, vo.x, s0x);
                lif_c(hy0, vin.y, vo.y, s0y);
                lif_c(hx1, vin.z, vo.z, s1x);
                lif_c(hy1, vin.w, vo.w, s1y);
                v2p[ma * 8 + na] = vo;
#pragma unroll
                for (int h = 0; h < 2; ++h) {
                    int rloc = mbase + ma * 16 + (lane >> 2) + h * 8;
                    int chunk = col0 >> 5, c32 = col0 & 31;
                    uint32_t addr = sb + S2OFF + chunk * 8192 + swz(rloc, c32 >> 3) + (c32 & 7) * 2;
                    uint32_t pk = (h == 0) ? pack_h2(__float2half_rn(s0x), __float2half_rn(s0y))
                                           : pack_h2(__float2half_rn(s1x), __float2half_rn(s1y));
                    asm volatile("st.shared.b32 [%0], %1;" :: "r"(addr), "r"(pk));
                }
            }
        }

        // ================= phase 3: h3 = s2 @ W3^T =================
        float acc3[2][4][4];
#pragma unroll
        for (int i = 0; i < 2; ++i)
#pragma unroll
            for (int j = 0; j < 4; ++j)
#pragma unroll
                for (int k = 0; k < 4; ++k) acc3[i][j][k] = 0.0f;

        for (int ks = 0; ks < 8; ++ks) {
            CP_WAIT0();
            __syncthreads();   // first iter also publishes s2
            if (ks + 1 < 8) { load_B3(ks + 1, (ks + 1) & 1); CP_COMMIT(); }
            uint32_t abase = sb + S2OFF + ks * 8192;
            uint32_t bbase = sb + B3OFF + (ks & 1) * 16384;
#pragma unroll
            for (int kk = 0; kk < 2; ++kk) {
                uint32_t a[8];
#pragma unroll
                for (int ma = 0; ma < 2; ++ma) {
                    uint32_t ad = abase + swz(a_row + ma * 16, kk * 2 + a_chb);
                    LDSM4(a[ma * 4 + 0], a[ma * 4 + 1], a[ma * 4 + 2], a[ma * 4 + 3], ad);
                }
#pragma unroll
                for (int pb = 0; pb < 2; ++pb) {
                    uint32_t b[8];
#pragma unroll
                    for (int h = 0; h < 2; ++h) {
                        uint32_t bd = bbase + pb * 8192 + swz(b3_row + h * 16, kk * 2 + b_chb);
                        LDSM4(b[h * 4 + 0], b[h * 4 + 1], b[h * 4 + 2], b[h * 4 + 3], bd);
                    }
#pragma unroll
                    for (int ma = 0; ma < 2; ++ma)
#pragma unroll
                        for (int na = 0; na < 4; ++na)
                            MMA16816(acc3[ma][na], &a[ma * 4], &b[na * 2]);
                }
            }
        }

        // ---- LIF3 epilogue -> out (+ v3 private) ----
#pragma unroll
        for (int ma = 0; ma < 2; ++ma) {
            int row0 = m0 + mbase + ma * 16 + (lane >> 2);
#pragma unroll
            for (int na = 0; na < 4; ++na) {
                int col0 = nbase2 + na * 8 + (lane & 3) * 2;
                if (col0 < O_) {
                    const float* a4 = acc3[ma][na];
                    float4 vin = (t == 0) ? make_float4(0.f, 0.f, 0.f, 0.f)
                                          : v3p[ma * 4 + na];
                    float4 vo;
                    float hx0 = __fadd_rn(__fmul_rn(a4[0], INV_S2), b3[col0]);
                    float hy0 = __fadd_rn(__fmul_rn(a4[1], INV_S2), b3[col0 + 1]);
                    float hx1 = __fadd_rn(__fmul_rn(a4[2], INV_S2), b3[col0]);
                    float hy1 = __fadd_rn(__fmul_rn(a4[3], INV_S2), b3[col0 + 1]);
                    float s0x, s0y, s1x, s1y;
                    lif_c(hx0, vin.x, vo.x, s0x);
                    lif_c(hy0, vin.y, vo.y, s0y);
                    lif_c(hx1, vin.z, vo.z, s1x);
                    lif_c(hy1, vin.w, vo.w, s1y);
                    v3p[ma * 4 + na] = vo;
                    *(float2*)(out + (size_t)row0 * O_ + col0) = make_float2(s0x, s0y);
                    *(float2*)(out + (size_t)(row0 + 8) * O_ + col0) = make_float2(s1x, s1y);
                }
            }
        }
    }
}

extern "C" void kernel_launch(void* const* d_in, const int* in_sizes, int n_in,
                              void* d_out, int out_size) {
    const float* dvs = (const float*)d_in[0];
    const float* W1  = (const float*)d_in[1];
    const float* b1  = (const float*)d_in[2];
    const float* W2  = (const float*)d_in[3];
    const float* b2  = (const float*)d_in[4];
    const float* W3  = (const float*)d_in[5];
    const float* b3  = (const float*)d_in[6];
    float* out = (float*)d_out;

    float *v1, *v2, *v3;
    __half *w1s, *w2s, *w3s;
    cudaGetSymbolAddress((void**)&v1, g_v1);
    cudaGetSymbolAddress((void**)&v2, g_v2);
    cudaGetSymbolAddress((void**)&v3, g_v3);
    cudaGetSymbolAddress((void**)&w1s, g_W1s);
    cudaGetSymbolAddress((void**)&w2s, g_W2s);
    cudaGetSymbolAddress((void**)&w3s, g_W3s);

    cudaFuncSetAttribute(mega_snn, cudaFuncAttributeMaxDynamicSharedMemorySize, SMEMM);

    split_w_kernel<<<(H_ * D_) / 256, 256>>>(W1, w1s, H_ * D_);
    split_w_kernel<<<(H_ * H_) / 256, 256>>>(W2, w2s, H_ * H_);
    split_w3_kernel<<<(128 * H_) / 256, 256>>>(W3);

    mega_snn<<<B_ / 128, 512, SMEMM>>>(dvs, w1s, w2s, w3s, b1, b2, b3,
                                       v1, v2, v3, out);
}

// round 14
// speedup vs baseline: 1.3511x; 1.3511x over previous
#include <cuda_runtime.h>
#include <cuda_fp16.h>
#include <cstdint>

// ---------------------------------------------------------------------------
// NeuroVPR SNN via mma.sync fp16 2-way exact-split (scale 2^6).
//  L1: 128Mx256N CTA tiles, 512 thr, 64-wide K stages (43 stages),
//      A triple-buffered (split pre-barrier), B double-buffered.
//  L2/L3 chain: R11-proven kernels, unchanged.
// ---------------------------------------------------------------------------

#define B_ 16384
#define T_ 3
#define D_ 2752
#define H_ 256
#define O_ 100

// ---- scratch ----
__device__ float g_h1[(size_t)B_ * T_ * H_];
__device__ float g_v1[(size_t)B_ * H_];
__device__ float g_v2[(size_t)B_ * H_];
__device__ float g_v3[(size_t)B_ * 128];
__device__ __half g_s1b[(size_t)B_ * H_];
__device__ __half g_s2b[(size_t)B_ * H_];
__device__ __half g_W1s[2 * H_ * D_];
__device__ __half g_W2s[2 * H_ * H_];
__device__ __half g_W3s[2 * 128 * H_];

#define WSCALE 64.0f
#define INV_S1 (1.0f / 4096.0f)
#define INV_S2 (1.0f / 64.0f)

// ======================= helpers =======================
__device__ __forceinline__ uint32_t smem_u32(const void* p) {
    uint32_t a;
    asm("{ .reg .u64 t; cvta.to.shared.u64 t, %1; cvt.u32.u64 %0, t; }"
        : "=r"(a) : "l"(p));
    return a;
}
#define CP_ASYNC16(dst, src) \
    asm volatile("cp.async.cg.shared.global [%0], [%1], 16;" :: "r"(dst), "l"(src))
#define CP_COMMIT() asm volatile("cp.async.commit_group;" ::: "memory")
#define CP_WAIT0() asm volatile("cp.async.wait_group 0;" ::: "memory")
#define CP_WAIT1() asm volatile("cp.async.wait_group 1;" ::: "memory")
#define LDSM4(r0, r1, r2, r3, addr) \
    asm volatile("ldmatrix.sync.aligned.m8n8.x4.shared.b16 {%0,%1,%2,%3}, [%4];" \
        : "=r"(r0), "=r"(r1), "=r"(r2), "=r"(r3) : "r"(addr))
#define MMA16816(d, a, b) \
    asm volatile("mma.sync.aligned.m16n8k16.row.col.f32.f16.f16.f32 " \
        "{%0,%1,%2,%3}, {%4,%5,%6,%7}, {%8,%9}, {%0,%1,%2,%3};" \
        : "+f"((d)[0]), "+f"((d)[1]), "+f"((d)[2]), "+f"((d)[3]) \
        : "r"((a)[0]), "r"((a)[1]), "r"((a)[2]), "r"((a)[3]), "r"((b)[0]), "r"((b)[1]))

__device__ __forceinline__ void split2(float x, __half& h, __half& l) {
    float xs = x * WSCALE;
    h = __float2half_rn(xs);
    l = __float2half_rn(xs - __half2float(h));
}
__device__ __forceinline__ uint32_t pack_h2(__half lo, __half hi) {
    return (uint32_t)__half_as_ushort(lo) | ((uint32_t)__half_as_ushort(hi) << 16);
}
__device__ __forceinline__ void lif_c(float hval, float vin, float& vout, float& sout) {
    float vn = __fadd_rn(vin, __fmul_rn(__fsub_rn(hval, vin), 0.5f));
    bool sp = (vn >= 1.0f);
    vout = sp ? 0.0f : vn;
    sout = sp ? 1.0f : 0.0f;
}
__device__ __forceinline__ uint32_t swz(int r, int c) {
    return (uint32_t)(r * 64 + ((c ^ ((r >> 1) & 3)) << 4));
}

// ======================= weight split kernels =======================
__global__ void split_w_kernel(const float* __restrict__ W, __half* dst, int n) {
    int i = blockIdx.x * 256 + threadIdx.x;
    __half h, l;
    split2(W[i], h, l);
    dst[i] = h; dst[i + n] = l;
}
__global__ void split_w3_kernel(const float* __restrict__ W3) {
    int i = blockIdx.x * 256 + threadIdx.x;
    int r = i >> 8, c = i & 255;
    float w = (r < O_) ? W3[r * H_ + c] : 0.0f;
    __half h, l;
    split2(w, h, l);
    g_W3s[i] = h; g_W3s[i + 128 * H_] = l;
}

// ======================= Layer-1 GEMM: 128Mx256N, 512 thr, 64-k stages ======
#define NST1 (D_ / 64)            // 43
#define ABUF_SZ 32768             // per A buffer: 2 planes x 2 q x 8192
#define BBUF_OFF 98304            // 3 A buffers before this
#define BBUF_SZ 65536             // per B buffer: 2 planes x 2 q x 16384
#define SMEM1 (BBUF_OFF + 2 * BBUF_SZ)   // 229376

__global__ void __launch_bounds__(512, 1) mma_gemm1(
    const float* __restrict__ Af32, const __half* __restrict__ Ws,
    const float* __restrict__ bias, float* __restrict__ Hout) {
    extern __shared__ char smem[];
    const uint32_t sb = smem_u32(smem);
    const int tid = threadIdx.x;
    const int lane = tid & 31;
    const int wid = tid >> 5;
    const int m0 = blockIdx.x * 128;
    const int mbase = (wid & 3) * 32;
    const int nbase = (wid >> 2) * 64;

    float acc[2][8][4];
#pragma unroll
    for (int i = 0; i < 2; ++i)
#pragma unroll
        for (int j = 0; j < 8; ++j)
#pragma unroll
            for (int k = 0; k < 4; ++k) acc[i][j][k] = 0.0f;

    float4 ra[4];                      // 16 fp32 = 64-k slice per thread-row
    const int lr = tid >> 2, lc = tid & 3;   // row, 16-k quarter

    auto ldg_A = [&](int ks) {
        const float* g = Af32 + (size_t)(m0 + lr) * D_ + ks * 64 + lc * 16;
        ra[0] = *(const float4*)g;
        ra[1] = *(const float4*)(g + 4);
        ra[2] = *(const float4*)(g + 8);
        ra[3] = *(const float4*)(g + 12);
    };
    // A buffer layout: plane p at p*16384, q-subchunk at +q*8192
    auto sts_A_split = [&](int abuf) {
        uint32_t ab = sb + abuf * ABUF_SZ;
        float x[16] = {ra[0].x, ra[0].y, ra[0].z, ra[0].w,
                       ra[1].x, ra[1].y, ra[1].z, ra[1].w,
                       ra[2].x, ra[2].y, ra[2].z, ra[2].w,
                       ra[3].x, ra[3].y, ra[3].z, ra[3].w};
        __half s0[16], s1[16];
#pragma unroll
        for (int j = 0; j < 16; ++j) split2(x[j], s0[j], s1[j]);
        const int q = lc >> 1, c0 = (lc & 1) * 2;
        uint32_t base = ab + q * 8192;
#pragma unroll
        for (int cc = 0; cc < 2; ++cc) {
            uint32_t off = swz(lr, c0 + cc);
            uint4 v0 = make_uint4(
                pack_h2(s0[cc * 8 + 0], s0[cc * 8 + 1]), pack_h2(s0[cc * 8 + 2], s0[cc * 8 + 3]),
                pack_h2(s0[cc * 8 + 4], s0[cc * 8 + 5]), pack_h2(s0[cc * 8 + 6], s0[cc * 8 + 7]));
            uint4 v1 = make_uint4(
                pack_h2(s1[cc * 8 + 0], s1[cc * 8 + 1]), pack_h2(s1[cc * 8 + 2], s1[cc * 8 + 3]),
                pack_h2(s1[cc * 8 + 4], s1[cc * 8 + 5]), pack_h2(s1[cc * 8 + 6], s1[cc * 8 + 7]));
            asm volatile("st.shared.v4.b32 [%0], {%1,%2,%3,%4};" :: "r"(base + off),
                         "r"(v0.x), "r"(v0.y), "r"(v0.z), "r"(v0.w));
            asm volatile("st.shared.v4.b32 [%0], {%1,%2,%3,%4};" :: "r"(base + 16384 + off),
                         "r"(v1.x), "r"(v1.y), "r"(v1.z), "r"(v1.w));
        }
    };
    // B buffer layout: plane p at p*32768, q at +q*16384
    auto load_B = [&](int ks, int bbuf) {
        uint32_t bb = sb + BBUF_OFF + bbuf * BBUF_SZ;
#pragma unroll
        for (int u = 0; u < 8; ++u) {
            int f = tid + u * 512;
            int s2 = f >> 10, rem = f & 1023, r = rem >> 2, c = rem & 3;
            int p = s2 >> 1, q = s2 & 1;
            const __half* src = Ws + (size_t)p * (H_ * D_) + (size_t)r * D_
                                + ks * 64 + q * 32 + c * 8;
            CP_ASYNC16(bb + p * 32768 + q * 16384 + swz(r, c), src);
        }
    };

    const int a_row = mbase + (lane & 7) + ((lane >> 3) & 1) * 8;
    const int a_chb = (lane >> 4);
    const int b_row = nbase + (lane & 7) + (lane >> 4) * 8;
    const int b_chb = ((lane >> 3) & 1);

    auto ldsmA = [&](uint32_t aq, int plane, int kk, uint32_t* dst) {
#pragma unroll
        for (int ma = 0; ma < 2; ++ma) {
            uint32_t ad = aq + plane * 16384 + swz(a_row + ma * 16, kk * 2 + a_chb);
            LDSM4(dst[ma * 4 + 0], dst[ma * 4 + 1], dst[ma * 4 + 2], dst[ma * 4 + 3], ad);
        }
    };
    auto ldsmB = [&](uint32_t bq, int pb, int kk, uint32_t* dst) {
#pragma unroll
        for (int h = 0; h < 4; ++h) {
            uint32_t bd = bq + pb * 32768 + swz(b_row + h * 16, kk * 2 + b_chb);
            LDSM4(dst[h * 4 + 0], dst[h * 4 + 1], dst[h * 4 + 2], dst[h * 4 + 3], bd);
        }
    };
    auto mmaP = [&](const uint32_t* a, const uint32_t* b) {
#pragma unroll
        for (int ma = 0; ma < 2; ++ma)
#pragma unroll
            for (int na = 0; na < 8; ++na)
                MMA16816(acc[ma][na], &a[ma * 4], &b[na * 2]);
    };

    // R11 software-pipelined body, run per 32-k subchunk q
    auto compute = [&](int abuf, int bbuf) {
        uint32_t ab = sb + abuf * ABUF_SZ;
        uint32_t bb = sb + BBUF_OFF + bbuf * BBUF_SZ;
#pragma unroll
        for (int q = 0; q < 2; ++q) {
            uint32_t aq = ab + q * 8192;
            uint32_t bq = bb + q * 16384;
            uint32_t a0[8], a1[8], a0n[8], bx[16], by[16];
            ldsmA(aq, 0, 0, a0);
            ldsmA(aq, 1, 0, a1);
            ldsmB(bq, 0, 0, bx);
            ldsmB(bq, 1, 0, by);
            mmaP(a0, bx);
            mmaP(a1, bx);
            ldsmA(aq, 0, 1, a0n);
            ldsmA(aq, 1, 1, a1);
            ldsmB(bq, 0, 1, bx);
            mmaP(a0, by);
            ldsmB(bq, 1, 1, by);
            mmaP(a0n, bx);
            mmaP(a1, bx);
            mmaP(a0n, by);
        }
    };

    // ---- prologue ----
    ldg_A(0); sts_A_split(0);
    load_B(0, 0); CP_COMMIT();
    ldg_A(1);

    // ---- main loop: one sync per 64-k stage ----
    for (int ks = 0; ks < NST1; ++ks) {
        int an = (ks + 1) % 3;
        if (ks + 1 < NST1) sts_A_split(an);          // 2 barriers from readers
        if (ks + 2 < NST1) ldg_A(ks + 2);
        CP_WAIT0();                                   // B(ks) resident
        __syncthreads();
        if (ks + 1 < NST1) { load_B(ks + 1, (ks + 1) & 1); CP_COMMIT(); }
        compute(ks % 3, ks & 1);
    }

    // ---- epilogue ----
#pragma unroll
    for (int ma = 0; ma < 2; ++ma) {
        int row0 = m0 + mbase + ma * 16 + (lane >> 2);
#pragma unroll
        for (int na = 0; na < 8; ++na) {
            int col0 = nbase + na * 8 + (lane & 3) * 2;
            const float* a4 = acc[ma][na];
#pragma unroll
            for (int h = 0; h < 2; ++h) {
                int row = row0 + h * 8;
                float cx = __fmul_rn(a4[h * 2 + 0], INV_S1);
                float cy = __fmul_rn(a4[h * 2 + 1], INV_S1);
                float2 o = make_float2(__fadd_rn(cx, bias[col0]),
                                       __fadd_rn(cy, bias[col0 + 1]));
                *(float2*)(Hout + (size_t)row * H_ + col0) = o;
            }
        }
    }
}

// ======================= L2/L3 GEMM: R11 verbatim ============
#define NST2 (H_ / 32)            // 8
#define APL2 8192
#define BPL2 8192
#define STG2 (APL2 + 2 * BPL2)    // 24576
#define SMEM2 (3 * STG2)          // 73728

template <int MODE>
__global__ void __launch_bounds__(256, 2) mma_gemm23(
    const __half* __restrict__ Ahf, const __half* __restrict__ Ws,
    const float* __restrict__ bias, __half* __restrict__ Sb,
    float* __restrict__ Sf, float* __restrict__ V, int t) {
    constexpr size_t PL = (MODE == 2) ? (size_t)H_ * H_ : (size_t)128 * H_;
    extern __shared__ char smem[];
    const uint32_t sb = smem_u32(smem);
    const int tid = threadIdx.x;
    const int lane = tid & 31;
    const int wid = tid >> 5;
    const int m0 = blockIdx.x * 128;
    const int n0 = blockIdx.y * 128;
    const int mbase = (wid >> 2) * 64;
    const int nbase = (wid & 3) * 32;

    float acc[4][4][4];
#pragma unroll
    for (int i = 0; i < 4; ++i)
#pragma unroll
        for (int j = 0; j < 4; ++j)
#pragma unroll
            for (int k = 0; k < 4; ++k) acc[i][j][k] = 0.0f;

    auto load_stage = [&](int ks, int buf) {
        int kc = ks * 32;
        uint32_t ab = sb + buf * STG2;
#pragma unroll
        for (int u = 0; u < 2; ++u) {
            int f = tid + u * 256;
            int r = f >> 2, c = f & 3;
            CP_ASYNC16(ab + swz(r, c), Ahf + (size_t)(m0 + r) * H_ + kc + c * 8);
        }
        uint32_t bb = ab + APL2;
#pragma unroll
        for (int u = 0; u < 4; ++u) {
            int f = tid + u * 256;
            int s = f >> 9, rem = f & 511, r = rem >> 2, c = rem & 3;
            const __half* src = Ws + (size_t)s * PL + (size_t)(n0 + r) * H_ + kc + c * 8;
            CP_ASYNC16(bb + s * BPL2 + swz(r, c), src);
        }
    };

    const int a_row = mbase + (lane & 7) + ((lane >> 3) & 1) * 8;
    const int a_chb = (lane >> 4);
    const int b_row = nbase + (lane & 7) + (lane >> 4) * 8;
    const int b_chb = ((lane >> 3) & 1);

    auto compute = [&](int buf) {
        uint32_t ab = sb + buf * STG2;
        uint32_t bb = ab + APL2;
#pragma unroll
        for (int kk = 0; kk < 2; ++kk) {
            uint32_t afr[4][4];
#pragma unroll
            for (int ma = 0; ma < 4; ++ma) {
                uint32_t ad = ab + swz(a_row + ma * 16, kk * 2 + a_chb);
                LDSM4(afr[ma][0], afr[ma][1], afr[ma][2], afr[ma][3], ad);
            }
#pragma unroll
            for (int pb = 0; pb < 2; ++pb) {
                uint32_t bfr[8];
#pragma unroll
                for (int h = 0; h < 2; ++h) {
                    uint32_t bd = bb + pb * BPL2 + swz(b_row + h * 16, kk * 2 + b_chb);
                    LDSM4(bfr[h * 4 + 0], bfr[h * 4 + 1], bfr[h * 4 + 2], bfr[h * 4 + 3], bd);
                }
#pragma unroll
                for (int ma = 0; ma < 4; ++ma)
#pragma unroll
                    for (int na = 0; na < 4; ++na)
                        MMA16816(acc[ma][na], afr[ma], &bfr[na * 2]);
            }
        }
    };

    load_stage(0, 0); CP_COMMIT();
    load_stage(1, 1); CP_COMMIT();

    int buf = 0;
    for (int ks = 0; ks < NST2; ++ks) {
        int b1 = (buf + 1 == 3) ? 0 : buf + 1;
        int b2 = (b1 + 1 == 3) ? 0 : b1 + 1;
        if (ks + 1 < NST2) { CP_WAIT1(); } else { CP_WAIT0(); }
        __syncthreads();
        if (ks + 2 < NST2) { load_stage(ks + 2, b2); CP_COMMIT(); }
        compute(buf);
        buf = b1;
    }

#pragma unroll
    for (int ma = 0; ma < 4; ++ma) {
        int row0 = m0 + mbase + ma * 16 + (lane >> 2);
#pragma unroll
        for (int na = 0; na < 4; ++na) {
            int col0 = n0 + nbase + na * 8 + (lane & 3) * 2;
            const float* a4 = acc[ma][na];
#pragma unroll
            for (int h = 0; h < 2; ++h) {
                int row = row0 + h * 8;
                float cx = __fmul_rn(a4[h * 2 + 0], INV_S2);
                float cy = __fmul_rn(a4[h * 2 + 1], INV_S2);
                if (MODE == 2) {
                    size_t idx = (size_t)row * H_ + col0;
                    float2 v = (t == 0) ? make_float2(0.f, 0.f) : *(float2*)(V + idx);
                    float hx = __fadd_rn(cx, bias[col0]);
                    float hy = __fadd_rn(cy, bias[col0 + 1]);
                    float vox, voy, sox, soy;
                    lif_c(hx, v.x, vox, sox);
                    lif_c(hy, v.y, voy, soy);
                    *(float2*)(V + idx) = make_float2(vox, voy);
                    *(uint32_t*)(Sb + idx) =
                        pack_h2(__float2half_rn(sox), __float2half_rn(soy));
                } else {
                    if (col0 < O_) {
                        size_t vidx = (size_t)row * 128 + col0;
                        float2 v = (t == 0) ? make_float2(0.f, 0.f) : *(float2*)(V + vidx);
                        float hx = __fadd_rn(cx, bias[col0]);
                        float hy = __fadd_rn(cy, bias[col0 + 1]);
                        float vox, voy, sox, soy;
                        lif_c(hx, v.x, vox, sox);
                        lif_c(hy, v.y, voy, soy);
                        *(float2*)(V + vidx) = make_float2(vox, voy);
                        *(float2*)(Sf + (size_t)row * O_ + col0) = make_float2(sox, soy);
                    }
                }
            }
        }
    }
}

// ======================= LIF layer 1 (R11 verbatim) =======================
__global__ void lif1_kernel(const float* __restrict__ h1, float* __restrict__ v1,
                            __half* __restrict__ s1, int t) {
    int i = blockIdx.x * blockDim.x + threadIdx.x;
    int e = i * 4;
    int b = e >> 8;
    int h = e & 255;
    float4 hv = *(const float4*)(h1 + (size_t)(b * 3 + t) * H_ + h);
    float4 v = (t == 0) ? make_float4(0.f, 0.f, 0.f, 0.f) : *(const float4*)(v1 + e);
    float4 vo, so;
    lif_c(hv.x, v.x, vo.x, so.x);
    lif_c(hv.y, v.y, vo.y, so.y);
    lif_c(hv.z, v.z, vo.z, so.z);
    lif_c(hv.w, v.w, vo.w, so.w);
    *(float4*)(v1 + e) = vo;
    uint2 sp;
    sp.x = pack_h2(__float2half_rn(so.x), __float2half_rn(so.y));
    sp.y = pack_h2(__float2half_rn(so.z), __float2half_rn(so.w));
    *(uint2*)(s1 + e) = sp;
}

extern "C" void kernel_launch(void* const* d_in, const int* in_sizes, int n_in,
                              void* d_out, int out_size) {
    const float* dvs = (const float*)d_in[0];
    const float* W1  = (const float*)d_in[1];
    const float* b1  = (const float*)d_in[2];
    const float* W2  = (const float*)d_in[3];
    const float* b2  = (const float*)d_in[4];
    const float* W3  = (const float*)d_in[5];
    const float* b3  = (const float*)d_in[6];
    float* out = (float*)d_out;

    float *h1, *v1, *v2, *v3;
    __half *s1b, *s2b, *w1s, *w2s, *w3s;
    cudaGetSymbolAddress((void**)&h1, g_h1);
    cudaGetSymbolAddress((void**)&v1, g_v1);
    cudaGetSymbolAddress((void**)&v2, g_v2);
    cudaGetSymbolAddress((void**)&v3, g_v3);
    cudaGetSymbolAddress((void**)&s1b, g_s1b);
    cudaGetSymbolAddress((void**)&s2b, g_s2b);
    cudaGetSymbolAddress((void**)&w1s, g_W1s);
    cudaGetSymbolAddress((void**)&w2s, g_W2s);
    cudaGetSymbolAddress((void**)&w3s, g_W3s);

    cudaFuncSetAttribute(mma_gemm1, cudaFuncAttributeMaxDynamicSharedMemorySize, SMEM1);
    cudaFuncSetAttribute(mma_gemm23<2>, cudaFuncAttributeMaxDynamicSharedMemorySize, SMEM2);
    cudaFuncSetAttribute(mma_gemm23<3>, cudaFuncAttributeMaxDynamicSharedMemorySize, SMEM2);

    split_w_kernel<<<(H_ * D_) / 256, 256>>>(W1, w1s, H_ * D_);
    split_w_kernel<<<(H_ * H_) / 256, 256>>>(W2, w2s, H_ * H_);
    split_w3_kernel<<<(128 * H_) / 256, 256>>>(W3);

    // layer 1, all timesteps: [B*T, D] @ W1^T -> g_h1  (128M x 256N tiles)
    mma_gemm1<<<(B_ * T_) / 128, 512, SMEM1>>>(dvs, w1s, b1, h1);

    for (int t = 0; t < T_; ++t) {
        lif1_kernel<<<(B_ * H_ / 4) / 256, 256>>>(h1, v1, s1b, t);
        mma_gemm23<2><<<dim3(B_ / 128, H_ / 128), 256, SMEM2>>>(
            s1b, w2s, b2, s2b, nullptr, v2, t);
        mma_gemm23<3><<<dim3(B_ / 128, 1), 256, SMEM2>>>(
            s2b, w3s, b3, nullptr, out, v3, t);
    }
}